// round 8
// baseline (speedup 1.0000x reference)
#include <cuda_runtime.h>

// AddDecomposedRelativePositions, fixed bench shapes:
// B=8, q_h=q_w=k_h=k_w=64, C=64, L=127 (rel idx = i-j+63)
//
// Single launch, three CTA roles by bid:
//  [0, B*64)        H-producer: bx=(b,h). out[w][kh] = q[bx] @ Rh(h)^T
//  [B*64, B*128)    W-producer: (b,w).    out[h][kw] = q[b,:,w,:] @ Rw(w)^T
//  [B*128, ...)     Consumer: one CTA per (bx,w) row, pure HBM stream.
// Producers: 4x4 register blocking, packed fma.rn.f32x2 (2 MACs/instr),
// publish to g_relh/g_relw + flag. Consumers front-issue streaming loads,
// spin on flags (hidden in DRAM latency shadow), combine, stream out.

#define THREADS 256
#define PAD 68

__device__ float g_relh[8 * 64 * 64 * 64];   // [bx][w][kh]
__device__ float g_relw[8 * 64 * 64 * 64];   // [bx][w][kw]
__device__ int   g_flagH[512];
__device__ int   g_flagW[512];

__device__ __forceinline__ unsigned long long pack2(float lo, float hi) {
    unsigned long long r;
    asm("mov.b64 %0, {%1, %2};" : "=l"(r) : "f"(lo), "f"(hi));
    return r;
}
__device__ __forceinline__ void fma2(unsigned long long& d,
                                     unsigned long long a,
                                     unsigned long long b) {
    asm("fma.rn.f32x2 %0, %1, %2, %0;" : "+l"(d) : "l"(a), "l"(b));
}
__device__ __forceinline__ float2 unpack2(unsigned long long v) {
    float2 f;
    asm("mov.b64 {%0, %1}, %2;" : "=f"(f.x), "=f"(f.y) : "l"(v));
    return f;
}

__global__ __launch_bounds__(THREADS, 6)
void fused_kernel(const float4* __restrict__ a4,
                  const float*  __restrict__ q,
                  const float*  __restrict__ rph,
                  const float*  __restrict__ rpw,
                  float4*       __restrict__ o4,
                  int B)
{
    extern __shared__ float smem[];          // 34816B: At[64][68] + Bt[64][68]
    const int t    = threadIdx.x;
    const int bid  = blockIdx.x;
    const int nH   = B * 64;
    const int nProd = 2 * nH;

    if (bid < nProd) {
        // ======================= PRODUCER =======================
        float* At = smem;             // At[c*PAD + r]
        float* Bt = smem + 64 * PAD;  // Bt[c*PAD + k]
        const bool isH = (bid < nH);

        float* outBase;               // + r*rowStride + k
        size_t rowStride;
        int*   flag;

        if (isH) {
            const int bx = bid;                 // b*64 + h
            const int h  = bx & 63;
            const float* qs = q + (size_t)bx * 4096;
            #pragma unroll 4
            for (int idx = t; idx < 4096; idx += THREADS) {
                int c = idx & 63, w = idx >> 6;
                At[c * PAD + w] = __ldg(&qs[idx]);     // r = w
            }
            #pragma unroll 4
            for (int idx = t; idx < 4096; idx += THREADS) {
                int c = idx & 63, kh = idx >> 6;
                Bt[c * PAD + kh] = __ldg(&rph[(h + 63 - kh) * 64 + c]);
            }
            outBase   = g_relh + (size_t)bx * 4096;    // [w][kh]
            rowStride = 64;
            flag      = &g_flagH[bx];
        } else {
            const int i2 = bid - nH;            // b*64 + w
            const int b  = i2 >> 6;
            const int w  = i2 & 63;
            #pragma unroll 4
            for (int idx = t; idx < 4096; idx += THREADS) {
                int c = idx & 63, h = idx >> 6;
                At[c * PAD + h] =
                    __ldg(&q[((size_t)(b * 4096 + h * 64 + w) << 6) + c]);  // r = h
            }
            #pragma unroll 4
            for (int idx = t; idx < 4096; idx += THREADS) {
                int c = idx & 63, kw = idx >> 6;
                Bt[c * PAD + kw] = __ldg(&rpw[(w + 63 - kw) * 64 + c]);
            }
            // out[h][kw] -> g_relw[(b*64+h)*64 + w][kw]: row stride (h) = 64*64
            outBase   = g_relw + ((size_t)(b * 4096 + w) << 6);
            rowStride = 4096;
            flag      = &g_flagW[i2];
        }
        __syncthreads();

        const int rb = t >> 4;        // 0..15  (output rows 4rb..4rb+3)
        const int kb = t & 15;        // 0..15  (output cols 4kb..4kb+3)

        unsigned long long acc[4][2];
        #pragma unroll
        for (int j = 0; j < 4; ++j) { acc[j][0] = 0ull; acc[j][1] = 0ull; }

        #pragma unroll 4
        for (int c = 0; c < 64; ++c) {
            float4 av = *(const float4*)&At[c * PAD + 4 * rb];
            float4 bv = *(const float4*)&Bt[c * PAD + 4 * kb];
            unsigned long long blo = pack2(bv.x, bv.y);
            unsigned long long bhi = pack2(bv.z, bv.w);
            float aj[4] = {av.x, av.y, av.z, av.w};
            #pragma unroll
            for (int j = 0; j < 4; ++j) {
                unsigned long long ad = pack2(aj[j], aj[j]);
                fma2(acc[j][0], ad, blo);
                fma2(acc[j][1], ad, bhi);
            }
        }

        #pragma unroll
        for (int j = 0; j < 4; ++j) {
            float2 lo = unpack2(acc[j][0]);
            float2 hi = unpack2(acc[j][1]);
            *(float4*)&outBase[(size_t)(4 * rb + j) * rowStride + 4 * kb] =
                make_float4(lo.x, lo.y, hi.x, hi.y);
        }

        __threadfence();
        __syncthreads();
        if (t == 0) *(volatile int*)flag = 1;
    } else {
        // ======================= CONSUMER =======================
        const int cta = bid - nProd;             // bx*64 + w
        const int bx  = cta >> 6;
        const int b   = bx >> 6;
        const int w   = cta & 63;

        const float4* ap = a4 + (size_t)cta * 1024;
        float4*       op = o4 + (size_t)cta * 1024;

        // front-batched streaming loads — independent of producers
        float4 a[4];
        #pragma unroll
        for (int k = 0; k < 4; ++k)
            a[k] = __ldcs(&ap[t + 256 * k]);

        if (t == 0) {
            while (*(volatile int*)&g_flagH[bx] == 0 ||
                   *(volatile int*)&g_flagW[b * 64 + w] == 0)
                __nanosleep(64);
        }
        __syncthreads();
        __threadfence();

        float4* rh4s = (float4*)smem;        // 16 float4 = rel_h row
        float4* rw4s = (float4*)smem + 16;   // 16 float4 = rel_w row
        if (t < 16)
            rh4s[t] = __ldg(&((const float4*)g_relh)[cta * 16 + t]);
        else if (t >= 32 && t < 48)
            rw4s[t - 32] = __ldg(&((const float4*)g_relw)[cta * 16 + (t - 32)]);
        __syncthreads();

        const float* rhf = (const float*)rh4s;
        #pragma unroll
        for (int k = 0; k < 4; ++k) {
            int idx = t + 256 * k;
            int kh  = idx >> 4;
            int kw4 = idx & 15;
            float  rh = rhf[kh];
            float4 rw = rw4s[kw4];
            float4 v  = a[k];
            v.x += rh + rw.x;
            v.y += rh + rw.y;
            v.z += rh + rw.z;
            v.w += rh + rw.w;
            __stcs(&op[idx], v);
        }
    }
}

extern "C" void kernel_launch(void* const* d_in, const int* in_sizes, int n_in,
                              void* d_out, int out_size)
{
    const float* attn = (const float*)d_in[0];
    const float* q    = (const float*)d_in[1];
    const float* rph  = (const float*)d_in[2];
    const float* rpw  = (const float*)d_in[3];
    float* out = (float*)d_out;

    const int B = in_sizes[0] / (4096 * 4096);       // 8 on the bench
    const int grid = 2 * B * 64 + B * 64 * 64;       // producers + consumers
    const int smem_bytes = 2 * 64 * PAD * sizeof(float);  // 34816

    fused_kernel<<<grid, THREADS, smem_bytes>>>(
        (const float4*)attn, q, rph, rpw, (float4*)out, B);
}

// round 9
// speedup vs baseline: 1.1105x; 1.1105x over previous
#include <cuda_runtime.h>

// AddDecomposedRelativePositions, fixed bench shapes:
// B=8, q_h=q_w=k_h=k_w=64, C=64, L=127 (rel idx = i-j+63)
//
// Kernel A (fast): 2*B*64 CTAs, each one non-redundant 64x64x64 GEMM.
//   bid < B*64 : H-producer for bx=(b,h): g_relh[bx][w][kh] = q[bx] @ Rh(h)^T
//   else       : W-producer for (b,w):    g_relw[(b,h)][w][kw] over h
//   4x4 register blocking with packed fma.rn.f32x2 (2 MACs/instr).
// Kernel B: proven stream kernel — one CTA per (bx,w) row, 1024 float4,
//   rel rows staged in 512B smem, LDG.128/STG.128 evict-first.

#define THREADS 256
#define PAD 68

__device__ float g_relh[8 * 64 * 64 * 64];   // [bx][w][kh]
__device__ float g_relw[8 * 64 * 64 * 64];   // [bx][w][kw]

__device__ __forceinline__ unsigned long long pack2(float lo, float hi) {
    unsigned long long r;
    asm("mov.b64 %0, {%1, %2};" : "=l"(r) : "f"(lo), "f"(hi));
    return r;
}
__device__ __forceinline__ void fma2(unsigned long long& d,
                                     unsigned long long a,
                                     unsigned long long b) {
    asm("fma.rn.f32x2 %0, %1, %2, %0;" : "+l"(d) : "l"(a), "l"(b));
}
__device__ __forceinline__ float2 unpack2(unsigned long long v) {
    float2 f;
    asm("mov.b64 {%0, %1}, %2;" : "=f"(f.x), "=f"(f.y) : "l"(v));
    return f;
}

__global__ __launch_bounds__(THREADS, 6)
void relpos_gemm_kernel(const float* __restrict__ q,
                        const float* __restrict__ rph,
                        const float* __restrict__ rpw,
                        int nH)
{
    extern __shared__ float smem[];   // At[64][68] + Bt[64][68] = 34816 B
    float* At = smem;                 // At[c*PAD + r]
    float* Bt = smem + 64 * PAD;      // Bt[c*PAD + k]

    const int t   = threadIdx.x;
    const int bid = blockIdx.x;
    const bool isH = (bid < nH);

    float* outBase;
    size_t rowStride;

    if (isH) {
        const int bx = bid;                 // b*64 + h
        const int h  = bx & 63;
        const float* qs = q + (size_t)bx * 4096;
        #pragma unroll 4
        for (int idx = t; idx < 4096; idx += THREADS) {
            int c = idx & 63, w = idx >> 6;
            At[c * PAD + w] = __ldg(&qs[idx]);            // r = w
        }
        #pragma unroll 4
        for (int idx = t; idx < 4096; idx += THREADS) {
            int c = idx & 63, kh = idx >> 6;
            Bt[c * PAD + kh] = __ldg(&rph[(h + 63 - kh) * 64 + c]);
        }
        outBase   = g_relh + (size_t)bx * 4096;           // [w][kh]
        rowStride = 64;
    } else {
        const int i2 = bid - nH;            // b*64 + w
        const int b  = i2 >> 6;
        const int w  = i2 & 63;
        #pragma unroll 4
        for (int idx = t; idx < 4096; idx += THREADS) {
            int c = idx & 63, h = idx >> 6;
            At[c * PAD + h] =
                __ldg(&q[((size_t)(b * 4096 + h * 64 + w) << 6) + c]);  // r = h
        }
        #pragma unroll 4
        for (int idx = t; idx < 4096; idx += THREADS) {
            int c = idx & 63, kw = idx >> 6;
            Bt[c * PAD + kw] = __ldg(&rpw[(w + 63 - kw) * 64 + c]);
        }
        outBase   = g_relw + ((size_t)(b * 4096 + w) << 6);  // row h stride 4096
        rowStride = 4096;
    }
    __syncthreads();

    const int rb = t >> 4;            // output rows 4rb..4rb+3
    const int kb = t & 15;            // output cols 4kb..4kb+3

    unsigned long long acc[4][2];
    #pragma unroll
    for (int j = 0; j < 4; ++j) { acc[j][0] = 0ull; acc[j][1] = 0ull; }

    #pragma unroll 4
    for (int c = 0; c < 64; ++c) {
        float4 av = *(const float4*)&At[c * PAD + 4 * rb];
        float4 bv = *(const float4*)&Bt[c * PAD + 4 * kb];
        unsigned long long blo = pack2(bv.x, bv.y);
        unsigned long long bhi = pack2(bv.z, bv.w);
        float aj[4] = {av.x, av.y, av.z, av.w};
        #pragma unroll
        for (int j = 0; j < 4; ++j) {
            unsigned long long ad = pack2(aj[j], aj[j]);
            fma2(acc[j][0], ad, blo);
            fma2(acc[j][1], ad, bhi);
        }
    }

    #pragma unroll
    for (int j = 0; j < 4; ++j) {
        float2 lo = unpack2(acc[j][0]);
        float2 hi = unpack2(acc[j][1]);
        *(float4*)&outBase[(size_t)(4 * rb + j) * rowStride + 4 * kb] =
            make_float4(lo.x, lo.y, hi.x, hi.y);
    }
}

// ---- Kernel B: one CTA per (bx, w) row; 1024 contiguous float4 each ----
__global__ __launch_bounds__(THREADS)
void stream_add_kernel(const float4* __restrict__ a4,
                       float4* __restrict__ o4)
{
    __shared__ float4 rh4s[16];   // rel_h row: 64 floats
    __shared__ float4 rw4s[16];   // rel_w row: 64 floats

    const int t   = threadIdx.x;
    const int cta = blockIdx.x;               // bx*64 + w

    const float4* ap = a4 + (size_t)cta * 1024;
    float4*       op = o4 + (size_t)cta * 1024;

    // front-batched streaming loads
    float4 a[4];
    #pragma unroll
    for (int k = 0; k < 4; ++k)
        a[k] = __ldcs(&ap[t + 256 * k]);

    if (t < 16)
        rh4s[t] = __ldg(&((const float4*)g_relh)[cta * 16 + t]);
    else if (t >= 32 && t < 48)
        rw4s[t - 32] = __ldg(&((const float4*)g_relw)[cta * 16 + (t - 32)]);
    __syncthreads();

    const float* rhf = (const float*)rh4s;

    #pragma unroll
    for (int k = 0; k < 4; ++k) {
        int idx = t + 256 * k;
        int kh  = idx >> 4;        // 0..63
        int kw4 = idx & 15;        // 0..15
        float  rh = rhf[kh];
        float4 rw = rw4s[kw4];
        float4 v  = a[k];
        v.x += rh + rw.x;
        v.y += rh + rw.y;
        v.z += rh + rw.z;
        v.w += rh + rw.w;
        __stcs(&op[idx], v);
    }
}

extern "C" void kernel_launch(void* const* d_in, const int* in_sizes, int n_in,
                              void* d_out, int out_size)
{
    const float* attn = (const float*)d_in[0];
    const float* q    = (const float*)d_in[1];
    const float* rph  = (const float*)d_in[2];
    const float* rpw  = (const float*)d_in[3];
    float* out = (float*)d_out;

    const int B  = in_sizes[0] / (4096 * 4096);   // 8 on the bench
    const int nH = B * 64;
    const int smem_bytes = 2 * 64 * PAD * sizeof(float);  // 34816

    cudaFuncSetAttribute(relpos_gemm_kernel,
                         cudaFuncAttributeMaxDynamicSharedMemorySize,
                         smem_bytes);

    relpos_gemm_kernel<<<2 * nH, THREADS, smem_bytes>>>(q, rph, rpw, nH);

    stream_add_kernel<<<B * 64 * 64, THREADS>>>(
        (const float4*)attn, (float4*)out);
}

// round 10
// speedup vs baseline: 1.1131x; 1.0023x over previous
#include <cuda_runtime.h>

// AddDecomposedRelativePositions, fixed bench shapes:
// B=8, q_h=q_w=k_h=k_w=64, C=64, L=127 (rel idx = i-j+63)
//
// Kernel A: 2*B*64 CTAs, each a non-redundant 64x64x64 GEMM.
//   fma.rn.f32x2 mainloop; B operands come pre-packed straight from the
//   LDS.128 (ulonglong2 reinterpret, zero MOVs) — only the broadcast A
//   operand is packed (4 packs/iter). Pipes balanced fma/alu ~16cyc/iter.
// Kernel B: proven stream kernel — one CTA per (bx,w) row, 1024 float4,
//   rel rows staged in 512B smem, LDG.128/STG.128 evict-first.

#define THREADS 256
#define PAD 68

__device__ float g_relh[8 * 64 * 64 * 64];   // [bx][w][kh]
__device__ float g_relw[8 * 64 * 64 * 64];   // [bx][w][kw]

__device__ __forceinline__ unsigned long long pack2(float lo, float hi) {
    unsigned long long r;
    asm("mov.b64 %0, {%1, %2};" : "=l"(r) : "f"(lo), "f"(hi));
    return r;
}
__device__ __forceinline__ void fma2(unsigned long long& d,
                                     unsigned long long a,
                                     unsigned long long b) {
    asm("fma.rn.f32x2 %0, %1, %2, %0;" : "+l"(d) : "l"(a), "l"(b));
}
__device__ __forceinline__ float2 unpack2(unsigned long long v) {
    float2 f;
    asm("mov.b64 {%0, %1}, %2;" : "=f"(f.x), "=f"(f.y) : "l"(v));
    return f;
}

__global__ __launch_bounds__(THREADS, 6)
void relpos_gemm_kernel(const float* __restrict__ q,
                        const float* __restrict__ rph,
                        const float* __restrict__ rpw,
                        int nH)
{
    extern __shared__ float smem[];   // At[64][68] + Bt[64][68] = 34816 B
    float* At = smem;                 // At[c*PAD + r]
    float* Bt = smem + 64 * PAD;      // Bt[c*PAD + k]

    const int t   = threadIdx.x;
    const int bid = blockIdx.x;
    const bool isH = (bid < nH);

    float* outBase;
    size_t rowStride;

    if (isH) {
        const int bx = bid;                 // b*64 + h
        const int h  = bx & 63;
        const float* qs = q + (size_t)bx * 4096;
        #pragma unroll 4
        for (int idx = t; idx < 4096; idx += THREADS) {
            int c = idx & 63, w = idx >> 6;
            At[c * PAD + w] = __ldg(&qs[idx]);            // r = w
        }
        #pragma unroll 4
        for (int idx = t; idx < 4096; idx += THREADS) {
            int c = idx & 63, kh = idx >> 6;
            Bt[c * PAD + kh] = __ldg(&rph[(h + 63 - kh) * 64 + c]);
        }
        outBase   = g_relh + (size_t)bx * 4096;           // [w][kh]
        rowStride = 64;
    } else {
        const int i2 = bid - nH;            // b*64 + w
        const int b  = i2 >> 6;
        const int w  = i2 & 63;
        #pragma unroll 4
        for (int idx = t; idx < 4096; idx += THREADS) {
            int c = idx & 63, h = idx >> 6;
            At[c * PAD + h] =
                __ldg(&q[((size_t)(b * 4096 + h * 64 + w) << 6) + c]);  // r = h
        }
        #pragma unroll 4
        for (int idx = t; idx < 4096; idx += THREADS) {
            int c = idx & 63, kw = idx >> 6;
            Bt[c * PAD + kw] = __ldg(&rpw[(w + 63 - kw) * 64 + c]);
        }
        outBase   = g_relw + ((size_t)(b * 4096 + w) << 6);  // row h stride 4096
        rowStride = 4096;
    }
    __syncthreads();

    const int rb = t >> 4;            // output rows 4rb..4rb+3
    const int kb = t & 15;            // output cols 4kb..4kb+3

    unsigned long long acc[4][2];
    #pragma unroll
    for (int j = 0; j < 4; ++j) { acc[j][0] = 0ull; acc[j][1] = 0ull; }

    #pragma unroll 4
    for (int c = 0; c < 64; ++c) {
        float4 av = *(const float4*)&At[c * PAD + 4 * rb];
        // B fragment: (b0,b1) and (b2,b3) are already packed pairs in smem
        ulonglong2 bv = *(const ulonglong2*)&Bt[c * PAD + 4 * kb];
        float aj[4] = {av.x, av.y, av.z, av.w};
        #pragma unroll
        for (int j = 0; j < 4; ++j) {
            unsigned long long ad = pack2(aj[j], aj[j]);
            fma2(acc[j][0], ad, bv.x);
            fma2(acc[j][1], ad, bv.y);
        }
    }

    #pragma unroll
    for (int j = 0; j < 4; ++j) {
        float2 lo = unpack2(acc[j][0]);
        float2 hi = unpack2(acc[j][1]);
        *(float4*)&outBase[(size_t)(4 * rb + j) * rowStride + 4 * kb] =
            make_float4(lo.x, lo.y, hi.x, hi.y);
    }
}

// ---- Kernel B: one CTA per (bx, w) row; 1024 contiguous float4 each ----
__global__ __launch_bounds__(THREADS)
void stream_add_kernel(const float4* __restrict__ a4,
                       float4* __restrict__ o4)
{
    __shared__ float4 rh4s[16];   // rel_h row: 64 floats
    __shared__ float4 rw4s[16];   // rel_w row: 64 floats

    const int t   = threadIdx.x;
    const int cta = blockIdx.x;               // bx*64 + w

    const float4* ap = a4 + (size_t)cta * 1024;
    float4*       op = o4 + (size_t)cta * 1024;

    // front-batched streaming loads
    float4 a[4];
    #pragma unroll
    for (int k = 0; k < 4; ++k)
        a[k] = __ldcs(&ap[t + 256 * k]);

    if (t < 16)
        rh4s[t] = __ldg(&((const float4*)g_relh)[cta * 16 + t]);
    else if (t >= 32 && t < 48)
        rw4s[t - 32] = __ldg(&((const float4*)g_relw)[cta * 16 + (t - 32)]);
    __syncthreads();

    const float* rhf = (const float*)rh4s;

    #pragma unroll
    for (int k = 0; k < 4; ++k) {
        int idx = t + 256 * k;
        int kh  = idx >> 4;        // 0..63
        int kw4 = idx & 15;        // 0..15
        float  rh = rhf[kh];
        float4 rw = rw4s[kw4];
        float4 v  = a[k];
        v.x += rh + rw.x;
        v.y += rh + rw.y;
        v.z += rh + rw.z;
        v.w += rh + rw.w;
        __stcs(&op[idx], v);
    }
}

extern "C" void kernel_launch(void* const* d_in, const int* in_sizes, int n_in,
                              void* d_out, int out_size)
{
    const float* attn = (const float*)d_in[0];
    const float* q    = (const float*)d_in[1];
    const float* rph  = (const float*)d_in[2];
    const float* rpw  = (const float*)d_in[3];
    float* out = (float*)d_out;

    const int B  = in_sizes[0] / (4096 * 4096);   // 8 on the bench
    const int nH = B * 64;
    const int smem_bytes = 2 * 64 * PAD * sizeof(float);  // 34816

    cudaFuncSetAttribute(relpos_gemm_kernel,
                         cudaFuncAttributeMaxDynamicSharedMemorySize,
                         smem_bytes);

    relpos_gemm_kernel<<<2 * nH, THREADS, smem_bytes>>>(q, rph, rpw, nH);

    stream_add_kernel<<<B * 64 * 64, THREADS>>>(
        (const float4*)attn, (float4*)out);
}